// round 17
// baseline (speedup 1.0000x reference)
#include <cuda_runtime.h>
#include <cuda_bf16.h>

#define N_NODES 5
#define EMB 16
#define HID 32

// LUT[c][e] : value for a cell whose game_state char == c, c in 0..5.
__device__ float g_lut[6 * EMB];

// ---------------------------------------------------------------------------
// Kernel 1: tiny GCN on 5 nodes -> fill g_lut. One block, 160 threads.
// Fires the programmatic-launch trigger at entry so the scatter kernel's
// blocks can begin (and prefetch gs) while this kernel runs.
// ---------------------------------------------------------------------------
__global__ void gcn_build_lut(const float* __restrict__ emb,   // [5,16]
                              const float* __restrict__ A,     // [5,5]
                              const float* __restrict__ W0,    // [32,16]
                              const float* __restrict__ W1,    // [32,32]
                              const float* __restrict__ W2,    // [32,32]
                              const float* __restrict__ Wf,    // [16,32]
                              const float* __restrict__ bf)    // [16]
{
    cudaTriggerProgrammaticLaunchCompletion();

    __shared__ float sE[N_NODES * EMB];
    __shared__ float sA[N_NODES * N_NODES];
    __shared__ float sW0[HID * EMB];
    __shared__ float sW1[HID * HID];
    __shared__ float sW2[HID * HID];
    __shared__ float sWf[EMB * HID];
    __shared__ float sbf[EMB];
    __shared__ float x0[N_NODES][EMB];
    __shared__ float h[N_NODES][HID];
    __shared__ float y[N_NODES][HID];

    const int t = threadIdx.x;
    const int NT = blockDim.x;

    for (int i = t; i < N_NODES * EMB; i += NT) sE[i] = emb[i];
    for (int i = t; i < N_NODES * N_NODES; i += NT) sA[i] = A[i];
    for (int i = t; i < HID * EMB; i += NT) sW0[i] = W0[i];
    for (int i = t; i < HID * HID; i += NT) sW1[i] = W1[i];
    for (int i = t; i < HID * HID; i += NT) sW2[i] = W2[i];
    for (int i = t; i < EMB * HID; i += NT) sWf[i] = Wf[i];
    for (int i = t; i < EMB; i += NT) sbf[i] = bf[i];
    __syncthreads();

    if (t < N_NODES * EMB) {
        int i = t / EMB, j = t % EMB;
        float s = 0.f;
        #pragma unroll
        for (int k = 0; k < N_NODES; k++) s += sA[i * N_NODES + k] * sE[k * EMB + j];
        x0[i][j] = s;
    }
    __syncthreads();

    // (single block: one warpgroup of 160 threads; per-thread smem reads are
    //  conflict-light and this runs once, so layout is not perf-critical)
    {
        int i = t / HID, o = t % HID;
        float s = 0.f;
        #pragma unroll
        for (int j = 0; j < EMB; j++) s += x0[i][j] * sW0[o * EMB + j];
        h[i][o] = fmaxf(s, 0.f);
    }
    __syncthreads();

    {
        int i = t / HID, o = t % HID;
        float s = 0.f;
        #pragma unroll
        for (int k = 0; k < N_NODES; k++) s += sA[i * N_NODES + k] * h[k][o];
        y[i][o] = s;
    }
    __syncthreads();
    {
        int i = t / HID, o = t % HID;
        float s = 0.f;
        #pragma unroll
        for (int j = 0; j < HID; j++) s += y[i][j] * sW1[o * HID + j];
        h[i][o] = fmaxf(s, 0.f);
    }
    __syncthreads();

    {
        int i = t / HID, o = t % HID;
        float s = 0.f;
        #pragma unroll
        for (int k = 0; k < N_NODES; k++) s += sA[i * N_NODES + k] * h[k][o];
        y[i][o] = s;
    }
    __syncthreads();
    {
        int i = t / HID, o = t % HID;
        float s = 0.f;
        #pragma unroll
        for (int j = 0; j < HID; j++) s += y[i][j] * sW2[o * HID + j];
        h[i][o] = fmaxf(s, 0.f);
    }
    __syncthreads();

    if (t < N_NODES * EMB) {
        int i = t / EMB, e = t % EMB;
        float s = sbf[e];
        #pragma unroll
        for (int j = 0; j < HID; j++) s += h[i][j] * sWf[e * HID + j];
        g_lut[(i + 1) * EMB + e] = s;
    }
    if (t < EMB) g_lut[t] = sE[t];
}

// ---------------------------------------------------------------------------
// Kernel 2: HBM-streaming scatter (best-measured shape: 8192 blocks, 45.4us),
// launched with PDL. Blocks start while kernel 1 runs: they issue their 8
// independent gs loads first, then griddepsync (LUT visible), then stream.
// ---------------------------------------------------------------------------
#define TPB 256
#define QPT 8
#define TILE (TPB * QPT)   // 2048 quads per block

__global__ void __launch_bounds__(TPB) scatter_lut(const int* __restrict__ gs,
                                                   float4* __restrict__ out,
                                                   int nquads)
{
    __shared__ float4 slut[6 * 4];   // 6 rows x 4 quads = 96 floats

    const int tid  = threadIdx.x;
    const int base = blockIdx.x * TILE + tid;   // quad index, iter 0
    const bool fast = (base + (QPT - 1) * TPB < nquads);

    // ---- prefetch gs while kernel 1 is still running ----
    int c[QPT];
    if (fast) {
        const int* __restrict__ g = gs + (base >> 2);
        #pragma unroll
        for (int u = 0; u < QPT; u++) c[u] = __ldg(g + u * (TPB >> 2));
    }

    // ---- wait for kernel 1's g_lut writes to be visible ----
    cudaGridDependencySynchronize();

    if (tid < 24) slut[tid] = reinterpret_cast<const float4*>(g_lut)[tid];
    __syncthreads();

    const int q = tid & 3;                      // lane-within-cell (TILE%4==0)
    const float4* __restrict__ lutq = slut + q;
    float4* __restrict__ o = out + base;

    if (fast) {
        #pragma unroll
        for (int u = 0; u < QPT; u++) {
            float4 v = lutq[c[u] * 4];
            __stcs(o + u * TPB, v);
        }
    } else {
        #pragma unroll
        for (int u = 0; u < QPT; u++) {
            int idx = base + u * TPB;
            if (idx < nquads) {
                int cc = __ldg(gs + (idx >> 2));
                __stcs(o + u * TPB, lutq[cc * 4]);
            }
        }
    }
}

// ---------------------------------------------------------------------------
extern "C" void kernel_launch(void* const* d_in, const int* in_sizes, int n_in,
                              void* d_out, int out_size)
{
    const int*   gs  = (const int*)d_in[0];    // game_state [256,128,128]
    const float* emb = (const float*)d_in[1];  // [5,16]
    const float* A   = (const float*)d_in[2];  // [5,5]
    const float* W0  = (const float*)d_in[3];  // [32,16]
    const float* W1  = (const float*)d_in[4];  // [32,32]
    const float* W2  = (const float*)d_in[5];  // [32,32]
    const float* Wf  = (const float*)d_in[6];  // [16,32]
    const float* bf  = (const float*)d_in[7];  // [16]
    float4* out = (float4*)d_out;

    const int ncells = in_sizes[0];            // 4,194,304
    const int nquads = ncells * 4;             // 16,777,216 float4 stores

    gcn_build_lut<<<1, 160>>>(emb, A, W0, W1, W2, Wf, bf);

    // scatter with programmatic dependent launch: overlaps its launch + gs
    // prefetch with kernel 1's execution.
    const int blocks = (nquads + TILE - 1) / TILE;   // 8192

    cudaLaunchConfig_t cfg = {};
    cfg.gridDim  = dim3(blocks, 1, 1);
    cfg.blockDim = dim3(TPB, 1, 1);
    cfg.dynamicSmemBytes = 0;
    cudaLaunchAttribute attr[1];
    attr[0].id = cudaLaunchAttributeProgrammaticStreamSerialization;
    attr[0].val.programmaticStreamSerializationAllowed = 1;
    cfg.attrs = attr;
    cfg.numAttrs = 1;

    cudaLaunchKernelEx(&cfg, scatter_lut, gs, out, nquads);
}